// round 5
// baseline (speedup 1.0000x reference)
#include <cuda_runtime.h>
#include <cstdint>
#include <math.h>

#define BS 512
#define NN 128
#define HEADS 8
#define DIN 64
#define DOUT 64

// dynamic smem (float indices), stride 68 rows
#define AST 68
#define A_HI 0
#define A_LO 8704
#define B_HI 17408
#define B_LO 21760
#define DSMEM_FLOATS 26112
#define DSMEM_BYTES (DSMEM_FLOATS * 4)

__device__ __forceinline__ float tanh_fast(float x) {
    float y;
    asm("tanh.approx.f32 %0, %1;" : "=f"(y) : "f"(x));
    return y;
}
// tf32 "hi" split by mantissa truncation (exactly what the MMA HW reads)
__device__ __forceinline__ float tf32_hi(float x) {
    return __uint_as_float(__float_as_uint(x) & 0xFFFFE000u);
}

__device__ __forceinline__ void mma_tf32(float c[4], const uint32_t a[4], const uint32_t b[2]) {
    asm volatile(
        "mma.sync.aligned.m16n8k8.row.col.f32.tf32.tf32.f32 "
        "{%0,%1,%2,%3}, {%4,%5,%6,%7}, {%8,%9}, {%0,%1,%2,%3};"
        : "+f"(c[0]), "+f"(c[1]), "+f"(c[2]), "+f"(c[3])
        : "r"(a[0]), "r"(a[1]), "r"(a[2]), "r"(a[3]), "r"(b[0]), "r"(b[1]));
}

__global__ __launch_bounds__(256)
void gat_mma(const float* __restrict__ h,
             const int* __restrict__ adj,
             const float* __restrict__ w,
             const float* __restrict__ a_src,
             const float* __restrict__ a_dst,
             const float* __restrict__ bias,
             float* __restrict__ out)
{
    extern __shared__ float dsm[];
    __shared__ float s_src[NN], s_dst[NN];
    __shared__ float s_asrc[DOUT], s_adst[DOUT], s_bias[DOUT];

    const int bh   = blockIdx.x;
    const int b    = bh >> 3;
    const int head = bh & 7;
    const int tid  = threadIdx.x;
    const int lane = tid & 31;
    const int wid  = tid >> 5;

    if (tid < DOUT) {
        s_asrc[tid] = a_src[head * DOUT + tid];
        s_adst[tid] = a_dst[head * DOUT + tid];
        s_bias[tid] = bias[tid];
    }

    // ---- convert A = h[b] (128x64) to tf32 hi/lo, row-major stride 68 ----
    {
        const float4* hg4 = (const float4*)(h + (size_t)b * NN * DIN);
        #pragma unroll
        for (int m = 0; m < 8; m++) {
            int i4  = tid + 256 * m;            // 2048 float4
            int row = i4 >> 4;                  // 16 float4 per row
            int c4  = i4 & 15;
            float4 v = hg4[i4];
            float4 hi, lo;
            hi.x = tf32_hi(v.x); lo.x = v.x - hi.x;
            hi.y = tf32_hi(v.y); lo.y = v.y - hi.y;
            hi.z = tf32_hi(v.z); lo.z = v.z - hi.z;
            hi.w = tf32_hi(v.w); lo.w = v.w - hi.w;
            int off = row * AST + c4 * 4;
            *(float4*)(dsm + A_HI + off) = hi;
            *(float4*)(dsm + A_LO + off) = lo;
        }
    }
    // ---- convert B = w[head] ([k][n] row-major, i.e. K-major per n-col) ----
    {
        const float4* wg4 = (const float4*)(w + (size_t)head * DIN * DOUT);
        #pragma unroll
        for (int m = 0; m < 4; m++) {
            int i4 = tid + 256 * m;             // 1024 float4
            int k  = i4 >> 4;
            int n4 = i4 & 15;
            float4 v = wg4[i4];
            float4 hi, lo;
            hi.x = tf32_hi(v.x); lo.x = v.x - hi.x;
            hi.y = tf32_hi(v.y); lo.y = v.y - hi.y;
            hi.z = tf32_hi(v.z); lo.z = v.z - hi.z;
            hi.w = tf32_hi(v.w); lo.w = v.w - hi.w;
            int off = k * AST + n4 * 4;
            *(float4*)(dsm + B_HI + off) = hi;
            *(float4*)(dsm + B_LO + off) = lo;
        }
    }
    __syncthreads();

    // ---- GEMM: warp tile 32x32. warp_m = wid>>1 (4), warp_n = wid&1 (2) ----
    const int wm = (wid >> 1) * 32;
    const int wn = (wid & 1) * 32;
    float c[2][4][4];
    #pragma unroll
    for (int mt = 0; mt < 2; mt++)
        #pragma unroll
        for (int nt = 0; nt < 4; nt++)
            #pragma unroll
            for (int e = 0; e < 4; e++) c[mt][nt][e] = 0.f;

    const int ar0 = wm + (lane >> 2);       // A frag row base
    const int akc = lane & 3;               // A frag k offset
    const int bn0 = wn + (lane >> 2);       // B frag n
    const int bkc = lane & 3;               // B frag k offset

    #pragma unroll
    for (int ks = 0; ks < 8; ks++) {
        const int k0 = ks * 8;
        uint32_t ah[2][4], al[2][4];
        #pragma unroll
        for (int mt = 0; mt < 2; mt++) {
            int r = ar0 + mt * 16;
            int base = r * AST + k0 + akc;
            ah[mt][0] = __float_as_uint(dsm[A_HI + base]);
            ah[mt][1] = __float_as_uint(dsm[A_HI + base + 8 * AST]);
            ah[mt][2] = __float_as_uint(dsm[A_HI + base + 4]);
            ah[mt][3] = __float_as_uint(dsm[A_HI + base + 8 * AST + 4]);
            al[mt][0] = __float_as_uint(dsm[A_LO + base]);
            al[mt][1] = __float_as_uint(dsm[A_LO + base + 8 * AST]);
            al[mt][2] = __float_as_uint(dsm[A_LO + base + 4]);
            al[mt][3] = __float_as_uint(dsm[A_LO + base + 8 * AST + 4]);
        }
        uint32_t bhf[4][2], blf[4][2];
        #pragma unroll
        for (int nt = 0; nt < 4; nt++) {
            int n = bn0 + nt * 8;
            int base = (k0 + bkc) * AST + n;
            bhf[nt][0] = __float_as_uint(dsm[B_HI + base]);
            bhf[nt][1] = __float_as_uint(dsm[B_HI + base + 4 * AST]);
            blf[nt][0] = __float_as_uint(dsm[B_LO + base]);
            blf[nt][1] = __float_as_uint(dsm[B_LO + base + 4 * AST]);
        }
        #pragma unroll
        for (int mt = 0; mt < 2; mt++)
            #pragma unroll
            for (int nt = 0; nt < 4; nt++) {
                mma_tf32(c[mt][nt], ah[mt], bhf[nt]);   // Ah*Bh
                mma_tf32(c[mt][nt], ah[mt], blf[nt]);   // Ah*Bl
                mma_tf32(c[mt][nt], al[mt], bhf[nt]);   // Al*Bh
            }
    }
    __syncthreads();   // all reads of A/B done before h_prime overlays A_HI

    // ---- write h_prime (overlay A_HI, stride 68) ----
    #pragma unroll
    for (int mt = 0; mt < 2; mt++) {
        int r = wm + mt * 16 + (lane >> 2);
        #pragma unroll
        for (int nt = 0; nt < 4; nt++) {
            int col = wn + nt * 8 + 2 * (lane & 3);
            *(float2*)(dsm + r * AST + col) = make_float2(c[mt][nt][0], c[mt][nt][1]);
            *(float2*)(dsm + (r + 8) * AST + col) = make_float2(c[mt][nt][2], c[mt][nt][3]);
        }
    }
    __syncthreads();

    // ---- tanh-dot: 8 warps, 16 rows each, 2 lanes/row (even/odd cols) ----
    {
        const int r = wid * 16 + (lane >> 1);
        const int p = lane & 1;
        const float* hp = dsm + r * AST;
        float ps = 0.f, pd = 0.f;
        #pragma unroll
        for (int cc = 0; cc < 32; cc++) {
            int col = 2 * cc + p;
            float t = tanh_fast(hp[col]);
            ps = fmaf(t, s_asrc[col], ps);
            pd = fmaf(t, s_adst[col], pd);
        }
        ps += __shfl_xor_sync(0xffffffffu, ps, 1);
        pd += __shfl_xor_sync(0xffffffffu, pd, 1);
        if (p == 0) { s_src[r] = ps; s_dst[r] = pd; }
    }
    __syncthreads();

    // ---- masked softmax (no max-shift; scores O(1)) + sparse aggregation ----
    const int* adjb = adj + (size_t)b * NN * NN;
    float* outp = out + (size_t)bh * NN * DOUT;

    for (int t = 0; t < 16; t++) {
        const int i = wid + 8 * t;
        const int* arow = adjb + i * NN;
        const float src_i = s_src[i];

        float pq[4];
        float denom = 0.f;
        #pragma unroll
        for (int q = 0; q < 4; q++) {
            const int j = q * 32 + lane;
            float e = src_i + s_dst[j];
            e = (e > 0.f) ? e : 0.2f * e;          // leaky_relu(0.2)
            pq[q] = arow[j] ? __expf(e) : 0.f;
            denom += pq[q];
        }
        #pragma unroll
        for (int o = 16; o >= 1; o >>= 1)
            denom += __shfl_xor_sync(0xffffffffu, denom, o);
        const float inv = (denom > 0.f) ? (1.0f / denom) : 0.f;

        float o0 = 0.f, o1 = 0.f;
        #pragma unroll
        for (int q = 0; q < 4; q++) {
            unsigned m = __ballot_sync(0xffffffffu, pq[q] > 0.f);
            while (m) {
                const int sl = __ffs(m) - 1;
                m &= m - 1;
                const float p = __shfl_sync(0xffffffffu, pq[q], sl);
                const int j = q * 32 + sl;
                o0 = fmaf(p, dsm[j * AST + lane], o0);
                o1 = fmaf(p, dsm[j * AST + 32 + lane], o1);
            }
        }
        outp[i * 64 + lane]      = fmaf(o0, inv, s_bias[lane]);
        outp[i * 64 + 32 + lane] = fmaf(o1, inv, s_bias[32 + lane]);
    }
}

extern "C" void kernel_launch(void* const* d_in, const int* in_sizes, int n_in,
                              void* d_out, int out_size) {
    const float* h     = (const float*)d_in[0];
    const int*   adj   = (const int*)d_in[1];
    const float* w     = (const float*)d_in[2];
    const float* a_src = (const float*)d_in[3];
    const float* a_dst = (const float*)d_in[4];
    const float* bias  = (const float*)d_in[5];
    float*       out   = (float*)d_out;

    static bool attr_set = false;
    if (!attr_set) {
        cudaFuncSetAttribute(gat_mma, cudaFuncAttributeMaxDynamicSharedMemorySize, DSMEM_BYTES);
        attr_set = true;
    }
    gat_mma<<<BS * HEADS, 256, DSMEM_BYTES>>>(h, adj, w, a_src, a_dst, bias, out);
}

// round 7
// speedup vs baseline: 1.4309x; 1.4309x over previous
#include <cuda_runtime.h>
#include <cuda_bf16.h>
#include <cstdint>
#include <math.h>

#define BS 512
#define NN 128
#define HEADS 8
#define DIN 64
#define DOUT 64

// ---- dynamic smem word (uint32/float) layout ----
// A planes: [128 rows][36 words] (each word = 2 consecutive-k bf16, 32 data + 4 pad)
// B planes: [64 n-rows][36 words]
#define PLANE_STRIDE 36
#define A_HI_W 0
#define A_LO_W 4608
#define B_HI_W 9216
#define B_LO_W 11520
#define SRC_W  13824
#define DST_W  13952
#define ASRC_W 14080
#define ADST_W 14144
#define BIAS_W 14208
#define TOTAL_W 14272
#define DSMEM_BYTES (TOTAL_W * 4)
// h_prime (fp32) overlays A region after GEMM: [128][66]
#define HP_STRIDE 66

__device__ __forceinline__ float tanh_fast(float x) {
    float y;
    asm("tanh.approx.f32 %0, %1;" : "=f"(y) : "f"(x));
    return y;
}

// split x into bf16 hi + bf16 lo
__device__ __forceinline__ void bf16_split(float x, uint16_t& hi, uint16_t& lo) {
    __nv_bfloat16 hb = __float2bfloat16(x);
    float hif = __bfloat162float(hb);
    hi  = __bfloat16_as_ushort(hb);
    lo  = __bfloat16_as_ushort(__float2bfloat16(x - hif));
}

__device__ __forceinline__ void mma_bf16(float c[4], const uint32_t a[4], const uint32_t b[2]) {
    asm volatile(
        "mma.sync.aligned.m16n8k16.row.col.f32.bf16.bf16.f32 "
        "{%0,%1,%2,%3}, {%4,%5,%6,%7}, {%8,%9}, {%0,%1,%2,%3};"
        : "+f"(c[0]), "+f"(c[1]), "+f"(c[2]), "+f"(c[3])
        : "r"(a[0]), "r"(a[1]), "r"(a[2]), "r"(a[3]), "r"(b[0]), "r"(b[1]));
}

__global__ __launch_bounds__(256, 4)
void gat_bf16(const float* __restrict__ h,
              const int* __restrict__ adj,
              const float* __restrict__ w,
              const float* __restrict__ a_src,
              const float* __restrict__ a_dst,
              const float* __restrict__ bias,
              float* __restrict__ out)
{
    extern __shared__ uint32_t dsw[];
    float* dsf = (float*)dsw;

    const int bh   = blockIdx.x;
    const int b    = bh >> 3;
    const int head = bh & 7;
    const int tid  = threadIdx.x;
    const int lane = tid & 31;
    const int wid  = tid >> 5;

    if (tid < DOUT) {
        dsf[ASRC_W + tid] = a_src[head * DOUT + tid];
        dsf[ADST_W + tid] = a_dst[head * DOUT + tid];
        dsf[BIAS_W + tid] = bias[tid];
    }

    // ---- A = h[b] (128x64) -> bf16 hi/lo planes ----
    {
        const float4* hg4 = (const float4*)(h + (size_t)b * NN * DIN);
        #pragma unroll
        for (int m = 0; m < 8; m++) {
            int i4  = tid + 256 * m;            // 2048 float4
            int row = i4 >> 4;
            int c4  = i4 & 15;
            float4 v = hg4[i4];
            uint16_t hx, lx, hy, ly, hz, lz, hw_, lw_;
            bf16_split(v.x, hx, lx);
            bf16_split(v.y, hy, ly);
            bf16_split(v.z, hz, lz);
            bf16_split(v.w, hw_, lw_);
            int off = row * PLANE_STRIDE + c4 * 2;
            uint2 hiw = make_uint2((uint32_t)hx | ((uint32_t)hy << 16),
                                   (uint32_t)hz | ((uint32_t)hw_ << 16));
            uint2 low = make_uint2((uint32_t)lx | ((uint32_t)ly << 16),
                                   (uint32_t)lz | ((uint32_t)lw_ << 16));
            *(uint2*)(dsw + A_HI_W + off) = hiw;
            *(uint2*)(dsw + A_LO_W + off) = low;
        }
    }
    // ---- B = w[head] ([k][n]) -> transposed bf16 planes [n][k] ----
    {
        const float4* wg4 = (const float4*)(w + (size_t)head * DIN * DOUT);
        __nv_bfloat16* bh16 = (__nv_bfloat16*)(dsw + B_HI_W);
        __nv_bfloat16* bl16 = (__nv_bfloat16*)(dsw + B_LO_W);
        #pragma unroll
        for (int m = 0; m < 4; m++) {
            int i4 = tid + 256 * m;             // 1024 float4
            int k  = i4 >> 4;
            int n4 = i4 & 15;
            float4 v = wg4[i4];
            float vv[4] = {v.x, v.y, v.z, v.w};
            #pragma unroll
            for (int e = 0; e < 4; e++) {
                int n = n4 * 4 + e;
                uint16_t hi, lo;
                bf16_split(vv[e], hi, lo);
                int idx = n * (PLANE_STRIDE * 2) + k;   // bf16 index, row stride 72
                bh16[idx] = __ushort_as_bfloat16(hi);
                bl16[idx] = __ushort_as_bfloat16(lo);
            }
        }
    }
    __syncthreads();

    // ---- GEMM: warp tile 32x32; wm = (wid>>1)*32, wn = (wid&1)*32 ----
    const int wm = (wid >> 1) * 32;
    const int wn = (wid & 1) * 32;
    float c[2][4][4];
    #pragma unroll
    for (int mt = 0; mt < 2; mt++)
        #pragma unroll
        for (int nt = 0; nt < 4; nt++)
            #pragma unroll
            for (int e = 0; e < 4; e++) c[mt][nt][e] = 0.f;

    const int arow = wm + (lane >> 2);
    const int kq   = lane & 3;

    #pragma unroll
    for (int ks = 0; ks < 4; ks++) {
        const int kw = ks * 8;                  // word offset for this k16 step
        uint32_t ah[2][4], al[2][4];
        #pragma unroll
        for (int mt = 0; mt < 2; mt++) {
            int base = (arow + mt * 16) * PLANE_STRIDE + kw + kq;
            ah[mt][0] = dsw[A_HI_W + base];
            ah[mt][1] = dsw[A_HI_W + base + 8 * PLANE_STRIDE];
            ah[mt][2] = dsw[A_HI_W + base + 4];
            ah[mt][3] = dsw[A_HI_W + base + 8 * PLANE_STRIDE + 4];
            al[mt][0] = dsw[A_LO_W + base];
            al[mt][1] = dsw[A_LO_W + base + 8 * PLANE_STRIDE];
            al[mt][2] = dsw[A_LO_W + base + 4];
            al[mt][3] = dsw[A_LO_W + base + 8 * PLANE_STRIDE + 4];
        }
        uint32_t bhf[4][2], blf[4][2];
        #pragma unroll
        for (int nt = 0; nt < 4; nt++) {
            int n = wn + nt * 8 + (lane >> 2);
            int base = n * PLANE_STRIDE + kw + kq;
            bhf[nt][0] = dsw[B_HI_W + base];
            bhf[nt][1] = dsw[B_HI_W + base + 4];
            blf[nt][0] = dsw[B_LO_W + base];
            blf[nt][1] = dsw[B_LO_W + base + 4];
        }
        #pragma unroll
        for (int mt = 0; mt < 2; mt++)
            #pragma unroll
            for (int nt = 0; nt < 4; nt++) {
                mma_bf16(c[mt][nt], ah[mt], bhf[nt]);
                mma_bf16(c[mt][nt], ah[mt], blf[nt]);
                mma_bf16(c[mt][nt], al[mt], bhf[nt]);
            }
    }
    __syncthreads();   // staging reads done before h_prime overlays A region

    // ---- h_prime (fp32, stride 66) overlays A planes ----
    #pragma unroll
    for (int mt = 0; mt < 2; mt++) {
        int r = wm + mt * 16 + (lane >> 2);
        #pragma unroll
        for (int nt = 0; nt < 4; nt++) {
            int col = wn + nt * 8 + 2 * (lane & 3);
            *(float2*)(dsf + r * HP_STRIDE + col) = make_float2(c[mt][nt][0], c[mt][nt][1]);
            *(float2*)(dsf + (r + 8) * HP_STRIDE + col) = make_float2(c[mt][nt][2], c[mt][nt][3]);
        }
    }
    __syncthreads();

    // ---- tanh-dot: 16 rows/warp, 2 lanes/row ----
    {
        const int r = wid * 16 + (lane >> 1);
        const int p = lane & 1;
        const float* hp = dsf + r * HP_STRIDE;
        float ps = 0.f, pd = 0.f;
        #pragma unroll
        for (int cc = 0; cc < 32; cc++) {
            int col = 2 * cc + p;
            float t = tanh_fast(hp[col]);
            ps = fmaf(t, dsf[ASRC_W + col], ps);
            pd = fmaf(t, dsf[ADST_W + col], pd);
        }
        ps += __shfl_xor_sync(0xffffffffu, ps, 1);
        pd += __shfl_xor_sync(0xffffffffu, pd, 1);
        if (p == 0) { dsf[SRC_W + r] = ps; dsf[DST_W + r] = pd; }
    }
    __syncthreads();

    // ---- masked softmax (scores O(1), no max-shift) + sparse aggregation ----
    const int* adjb = adj + (size_t)b * NN * NN;
    float* outp = out + (size_t)bh * NN * DOUT;

    for (int t = 0; t < 16; t++) {
        const int i = wid + 8 * t;
        const int* arow2 = adjb + i * NN;
        const float src_i = dsf[SRC_W + i];

        float pq[4];
        float denom = 0.f;
        #pragma unroll
        for (int q = 0; q < 4; q++) {
            const int j = q * 32 + lane;
            float e = src_i + dsf[DST_W + j];
            e = (e > 0.f) ? e : 0.2f * e;          // leaky_relu(0.2)
            pq[q] = arow2[j] ? __expf(e) : 0.f;
            denom += pq[q];
        }
        #pragma unroll
        for (int o = 16; o >= 1; o >>= 1)
            denom += __shfl_xor_sync(0xffffffffu, denom, o);
        const float inv = (denom > 0.f) ? (1.0f / denom) : 0.f;

        float o0 = 0.f, o1 = 0.f;
        #pragma unroll
        for (int q = 0; q < 4; q++) {
            unsigned m = __ballot_sync(0xffffffffu, pq[q] > 0.f);
            while (m) {
                const int sl = __ffs(m) - 1;
                m &= m - 1;
                const float p = __shfl_sync(0xffffffffu, pq[q], sl);
                const int j = q * 32 + sl;
                o0 = fmaf(p, dsf[j * HP_STRIDE + lane], o0);
                o1 = fmaf(p, dsf[j * HP_STRIDE + 32 + lane], o1);
            }
        }
        outp[i * 64 + lane]      = fmaf(o0, inv, dsf[BIAS_W + lane]);
        outp[i * 64 + 32 + lane] = fmaf(o1, inv, dsf[BIAS_W + 32 + lane]);
    }
}

extern "C" void kernel_launch(void* const* d_in, const int* in_sizes, int n_in,
                              void* d_out, int out_size) {
    const float* h     = (const float*)d_in[0];
    const int*   adj   = (const int*)d_in[1];
    const float* w     = (const float*)d_in[2];
    const float* a_src = (const float*)d_in[3];
    const float* a_dst = (const float*)d_in[4];
    const float* bias  = (const float*)d_in[5];
    float*       out   = (float*)d_out;

    static bool attr_set = false;
    if (!attr_set) {
        cudaFuncSetAttribute(gat_bf16, cudaFuncAttributeMaxDynamicSharedMemorySize, DSMEM_BYTES);
        attr_set = true;
    }
    gat_bf16<<<BS * HEADS, 256, DSMEM_BYTES>>>(h, adj, w, a_src, a_dst, bias, out);
}

// round 9
// speedup vs baseline: 1.8650x; 1.3034x over previous
#include <cuda_runtime.h>
#include <cuda_fp16.h>
#include <cuda_bf16.h>
#include <cstdint>
#include <math.h>

#define BS 512
#define NN 128
#define HEADS 8
#define DIN 64
#define DOUT 64

// ---- dynamic smem word layout ----
// Phase A (staging, dead after GEMM1):
#define PLANE_STRIDE 36
#define A_HI_W 0
#define A_LO_W 4608
#define B_HI_W 9216
#define B_LO_W 11520
// Phase B (overlays staging):
//   P  [128 i][68 words]  fp16 pairs, stride 68
//   HT [64 o][68 words]   fp16 h_prime^T
//   RED[128][2] ps + [128][2] pd fp32 partials
#define P_W    0
#define HT_W   8704
#define RED_W  13056
// persistent:
#define SRC_W  13824
#define DST_W  13952
#define BIAS_W 14080
#define TOTAL_W 14144
#define DSMEM_BYTES (TOTAL_W * 4)

__device__ __forceinline__ float tanh_fast(float x) {
    float y;
    asm("tanh.approx.f32 %0, %1;" : "=f"(y) : "f"(x));
    return y;
}
__device__ __forceinline__ void bf16_split(float x, uint16_t& hi, uint16_t& lo) {
    __nv_bfloat16 hb = __float2bfloat16(x);
    float hif = __bfloat162float(hb);
    hi  = __bfloat16_as_ushort(hb);
    lo  = __bfloat16_as_ushort(__float2bfloat16(x - hif));
}
__device__ __forceinline__ void mma_bf16(float c[4], const uint32_t a[4], const uint32_t b[2]) {
    asm volatile(
        "mma.sync.aligned.m16n8k16.row.col.f32.bf16.bf16.f32 "
        "{%0,%1,%2,%3}, {%4,%5,%6,%7}, {%8,%9}, {%0,%1,%2,%3};"
        : "+f"(c[0]), "+f"(c[1]), "+f"(c[2]), "+f"(c[3])
        : "r"(a[0]), "r"(a[1]), "r"(a[2]), "r"(a[3]), "r"(b[0]), "r"(b[1]));
}
__device__ __forceinline__ void mma_fp16(float c[4], const uint32_t a[4], const uint32_t b[2]) {
    asm volatile(
        "mma.sync.aligned.m16n8k16.row.col.f32.f16.f16.f32 "
        "{%0,%1,%2,%3}, {%4,%5,%6,%7}, {%8,%9}, {%0,%1,%2,%3};"
        : "+f"(c[0]), "+f"(c[1]), "+f"(c[2]), "+f"(c[3])
        : "r"(a[0]), "r"(a[1]), "r"(a[2]), "r"(a[3]), "r"(b[0]), "r"(b[1]));
}

__global__ __launch_bounds__(256, 4)
void gat_tc2(const float* __restrict__ h,
             const int* __restrict__ adj,
             const float* __restrict__ w,
             const float* __restrict__ a_src,
             const float* __restrict__ a_dst,
             const float* __restrict__ bias,
             float* __restrict__ out)
{
    extern __shared__ uint32_t dsw[];
    float* dsf = (float*)dsw;

    const int bh   = blockIdx.x;
    const int b    = bh >> 3;
    const int head = bh & 7;
    const int tid  = threadIdx.x;
    const int lane = tid & 31;
    const int wid  = tid >> 5;

    if (tid < DOUT) dsf[BIAS_W + tid] = bias[tid];

    // ---- stage A = h[b] (128x64) -> bf16 hi/lo planes ----
    {
        const float4* hg4 = (const float4*)(h + (size_t)b * NN * DIN);
        #pragma unroll
        for (int m = 0; m < 8; m++) {
            int i4  = tid + 256 * m;
            int row = i4 >> 4;
            int c4  = i4 & 15;
            float4 v = hg4[i4];
            uint16_t hx, lx, hy, ly, hz, lz, hw_, lw_;
            bf16_split(v.x, hx, lx);
            bf16_split(v.y, hy, ly);
            bf16_split(v.z, hz, lz);
            bf16_split(v.w, hw_, lw_);
            int off = row * PLANE_STRIDE + c4 * 2;
            *(uint2*)(dsw + A_HI_W + off) = make_uint2((uint32_t)hx | ((uint32_t)hy << 16),
                                                       (uint32_t)hz | ((uint32_t)hw_ << 16));
            *(uint2*)(dsw + A_LO_W + off) = make_uint2((uint32_t)lx | ((uint32_t)ly << 16),
                                                       (uint32_t)lz | ((uint32_t)lw_ << 16));
        }
    }
    // ---- stage B = w[head] ([k][n]) -> transposed bf16 planes [n][k] ----
    {
        const float4* wg4 = (const float4*)(w + (size_t)head * DIN * DOUT);
        __nv_bfloat16* bh16 = (__nv_bfloat16*)(dsw + B_HI_W);
        __nv_bfloat16* bl16 = (__nv_bfloat16*)(dsw + B_LO_W);
        #pragma unroll
        for (int m = 0; m < 4; m++) {
            int i4 = tid + 256 * m;
            int k  = i4 >> 4;
            int n4 = i4 & 15;
            float4 v = wg4[i4];
            float vv[4] = {v.x, v.y, v.z, v.w};
            #pragma unroll
            for (int e = 0; e < 4; e++) {
                int n = n4 * 4 + e;
                uint16_t hi, lo;
                bf16_split(vv[e], hi, lo);
                int idx = n * (PLANE_STRIDE * 2) + k;
                bh16[idx] = __ushort_as_bfloat16(hi);
                bl16[idx] = __ushort_as_bfloat16(lo);
            }
        }
    }
    __syncthreads();   // S1

    // ---- GEMM1: h_prime = A @ B, warp tile 32x32 ----
    const int wm = (wid >> 1) * 32;
    const int wn = (wid & 1) * 32;
    float c[2][4][4];
    #pragma unroll
    for (int mt = 0; mt < 2; mt++)
        #pragma unroll
        for (int nt = 0; nt < 4; nt++)
            #pragma unroll
            for (int e = 0; e < 4; e++) c[mt][nt][e] = 0.f;

    const int arow = wm + (lane >> 2);
    const int kq   = lane & 3;

    #pragma unroll
    for (int ks = 0; ks < 4; ks++) {
        const int kw = ks * 8;
        uint32_t ah[2][4], al[2][4];
        #pragma unroll
        for (int mt = 0; mt < 2; mt++) {
            int base = (arow + mt * 16) * PLANE_STRIDE + kw + kq;
            ah[mt][0] = dsw[A_HI_W + base];
            ah[mt][1] = dsw[A_HI_W + base + 8 * PLANE_STRIDE];
            ah[mt][2] = dsw[A_HI_W + base + 4];
            ah[mt][3] = dsw[A_HI_W + base + 8 * PLANE_STRIDE + 4];
            al[mt][0] = dsw[A_LO_W + base];
            al[mt][1] = dsw[A_LO_W + base + 8 * PLANE_STRIDE];
            al[mt][2] = dsw[A_LO_W + base + 4];
            al[mt][3] = dsw[A_LO_W + base + 8 * PLANE_STRIDE + 4];
        }
        uint32_t bhf[4][2], blf[4][2];
        #pragma unroll
        for (int nt = 0; nt < 4; nt++) {
            int n = wn + nt * 8 + (lane >> 2);
            int base = n * PLANE_STRIDE + kw + kq;
            bhf[nt][0] = dsw[B_HI_W + base];
            bhf[nt][1] = dsw[B_HI_W + base + 4];
            blf[nt][0] = dsw[B_LO_W + base];
            blf[nt][1] = dsw[B_LO_W + base + 4];
        }
        #pragma unroll
        for (int mt = 0; mt < 2; mt++)
            #pragma unroll
            for (int nt = 0; nt < 4; nt++) {
                mma_bf16(c[mt][nt], ah[mt], bhf[nt]);
                mma_bf16(c[mt][nt], ah[mt], blf[nt]);
                mma_bf16(c[mt][nt], al[mt], bhf[nt]);
            }
    }
    __syncthreads();   // S2: staging dead, region becomes P/HT/RED

    // ---- HT = h_prime^T fp16 [o][j], directly from register fragments ----
    {
        __half* hptr = (__half*)(dsw + HT_W);
        #pragma unroll
        for (int mt = 0; mt < 2; mt++) {
            int ja = wm + mt * 16 + (lane >> 2);
            #pragma unroll
            for (int nt = 0; nt < 4; nt++) {
                int o0 = wn + nt * 8 + 2 * (lane & 3);
                hptr[o0 * 136 + ja]           = __float2half(c[mt][nt][0]);
                hptr[(o0 + 1) * 136 + ja]     = __float2half(c[mt][nt][1]);
                hptr[o0 * 136 + ja + 8]       = __float2half(c[mt][nt][2]);
                hptr[(o0 + 1) * 136 + ja + 8] = __float2half(c[mt][nt][3]);
            }
        }
    }
    // ---- tanh-dot partials from registers (quad-shuffle reduce) ----
    {
        float2 as2[4], ad2[4];
        #pragma unroll
        for (int nt = 0; nt < 4; nt++) {
            int o0 = wn + nt * 8 + 2 * (lane & 3);
            as2[nt] = *(const float2*)&a_src[head * DOUT + o0];
            ad2[nt] = *(const float2*)&a_dst[head * DOUT + o0];
        }
        #pragma unroll
        for (int mt = 0; mt < 2; mt++) {
            float psA = 0.f, pdA = 0.f, psB = 0.f, pdB = 0.f;
            #pragma unroll
            for (int nt = 0; nt < 4; nt++) {
                float t0 = tanh_fast(c[mt][nt][0]);
                float t1 = tanh_fast(c[mt][nt][1]);
                float t2 = tanh_fast(c[mt][nt][2]);
                float t3 = tanh_fast(c[mt][nt][3]);
                psA = fmaf(t0, as2[nt].x, fmaf(t1, as2[nt].y, psA));
                pdA = fmaf(t0, ad2[nt].x, fmaf(t1, ad2[nt].y, pdA));
                psB = fmaf(t2, as2[nt].x, fmaf(t3, as2[nt].y, psB));
                pdB = fmaf(t2, ad2[nt].x, fmaf(t3, ad2[nt].y, pdB));
            }
            #pragma unroll
            for (int o = 1; o <= 2; o <<= 1) {
                psA += __shfl_xor_sync(0xffffffffu, psA, o);
                pdA += __shfl_xor_sync(0xffffffffu, pdA, o);
                psB += __shfl_xor_sync(0xffffffffu, psB, o);
                pdB += __shfl_xor_sync(0xffffffffu, pdB, o);
            }
            if ((lane & 3) == 0) {
                int ra = wm + mt * 16 + (lane >> 2);
                int hf = wid & 1;
                dsf[RED_W + ra * 2 + hf]             = psA;
                dsf[RED_W + 256 + ra * 2 + hf]       = pdA;
                dsf[RED_W + (ra + 8) * 2 + hf]       = psB;
                dsf[RED_W + 256 + (ra + 8) * 2 + hf] = pdB;
            }
        }
    }
    __syncthreads();   // S3
    if (tid < NN) {
        dsf[SRC_W + tid] = dsf[RED_W + tid * 2] + dsf[RED_W + tid * 2 + 1];
        dsf[DST_W + tid] = dsf[RED_W + 256 + tid * 2] + dsf[RED_W + 256 + tid * 2 + 1];
    }
    __syncthreads();   // S4

    // ---- P pass: one warp per 16 rows; lane owns j = 4*lane .. 4*lane+3 ----
    {
        const int4* adjb4 = (const int4*)(adj + (size_t)b * NN * NN);
        #pragma unroll 1
        for (int t = 0; t < 16; t++) {
            const int i = wid * 16 + t;
            int4 av = adjb4[i * 32 + lane];
            float4 dv = *(const float4*)&dsf[DST_W + 4 * lane];
            const float src_i = dsf[SRC_W + i];

            float e0 = src_i + dv.x; e0 = (e0 > 0.f) ? e0 : 0.2f * e0;
            float e1 = src_i + dv.y; e1 = (e1 > 0.f) ? e1 : 0.2f * e1;
            float e2 = src_i + dv.z; e2 = (e2 > 0.f) ? e2 : 0.2f * e2;
            float e3 = src_i + dv.w; e3 = (e3 > 0.f) ? e3 : 0.2f * e3;
            float p0 = av.x ? __expf(e0) : 0.f;
            float p1 = av.y ? __expf(e1) : 0.f;
            float p2 = av.z ? __expf(e2) : 0.f;
            float p3 = av.w ? __expf(e3) : 0.f;
            float d = p0 + p1 + p2 + p3;
            #pragma unroll
            for (int o = 16; o >= 1; o >>= 1)
                d += __shfl_xor_sync(0xffffffffu, d, o);
            const float inv = (d > 0.f) ? (1.0f / d) : 0.f;

            __half2 h01 = __floats2half2_rn(p0 * inv, p1 * inv);
            __half2 h23 = __floats2half2_rn(p2 * inv, p3 * inv);
            *(uint2*)(dsw + P_W + i * 68 + 2 * lane) =
                make_uint2(*(uint32_t*)&h01, *(uint32_t*)&h23);
        }
    }
    __syncthreads();   // S5

    // ---- GEMM2: out = P @ HT^T  (M=128 i, N=64 o, K=128 j), fp16 ----
    float c2[2][4][4];
    #pragma unroll
    for (int mt = 0; mt < 2; mt++)
        #pragma unroll
        for (int nt = 0; nt < 4; nt++)
            #pragma unroll
            for (int e = 0; e < 4; e++) c2[mt][nt][e] = 0.f;

    #pragma unroll
    for (int ks = 0; ks < 8; ks++) {
        const int kw = ks * 8;
        uint32_t af[2][4];
        #pragma unroll
        for (int mt = 0; mt < 2; mt++) {
            int base = (wm + mt * 16 + (lane >> 2)) * 68 + kw + kq;
            af[mt][0] = dsw[P_W + base];
            af[mt][1] = dsw[P_W + base + 8 * 68];
            af[mt][2] = dsw[P_W + base + 4];
            af[mt][3] = dsw[P_W + base + 8 * 68 + 4];
        }
        uint32_t bf[4][2];
        #pragma unroll
        for (int nt = 0; nt < 4; nt++) {
            int o = wn + nt * 8 + (lane >> 2);
            int base = o * 68 + kw + kq;
            bf[nt][0] = dsw[HT_W + base];
            bf[nt][1] = dsw[HT_W + base + 4];
        }
        #pragma unroll
        for (int mt = 0; mt < 2; mt++)
            #pragma unroll
            for (int nt = 0; nt < 4; nt++)
                mma_fp16(c2[mt][nt], af[mt], bf[nt]);
    }

    // ---- epilogue: + bias, write out ----
    {
        float* outp = out + (size_t)bh * NN * DOUT;
        #pragma unroll
        for (int nt = 0; nt < 4; nt++) {
            int o0 = wn + nt * 8 + 2 * (lane & 3);
            float2 bv = *(const float2*)&dsf[BIAS_W + o0];
            #pragma unroll
            for (int mt = 0; mt < 2; mt++) {
                int ra = wm + mt * 16 + (lane >> 2);
                *(float2*)&outp[ra * DOUT + o0] =
                    make_float2(c2[mt][nt][0] + bv.x, c2[mt][nt][1] + bv.y);
                *(float2*)&outp[(ra + 8) * DOUT + o0] =
                    make_float2(c2[mt][nt][2] + bv.x, c2[mt][nt][3] + bv.y);
            }
        }
    }
}

extern "C" void kernel_launch(void* const* d_in, const int* in_sizes, int n_in,
                              void* d_out, int out_size) {
    const float* h     = (const float*)d_in[0];
    const int*   adj   = (const int*)d_in[1];
    const float* w     = (const float*)d_in[2];
    const float* a_src = (const float*)d_in[3];
    const float* a_dst = (const float*)d_in[4];
    const float* bias  = (const float*)d_in[5];
    float*       out   = (float*)d_out;

    static bool attr_set = false;
    if (!attr_set) {
        cudaFuncSetAttribute(gat_tc2, cudaFuncAttributeMaxDynamicSharedMemorySize, DSMEM_BYTES);
        attr_set = true;
    }
    gat_tc2<<<BS * HEADS, 256, DSMEM_BYTES>>>(h, adj, w, a_src, a_dst, bias, out);
}